// round 14
// baseline (speedup 1.0000x reference)
#include <cuda_runtime.h>
#include <cuda_fp16.h>
#include <cstdint>

#define NN 4096
#define NB 32
#define PA 3072      /* u32 per fp16 fragment panel (48-k) */
#define P8 2048      /* u32 per int8 fragment panel (64-k) */
#define PW 1024      /* u32 per vw B-frag panel */
#define QBUF 2304    /* padded pass1 smem buffer stride (u32) */
#define SCALE2 (0.28867513459481287f * 1.4426950408889634f)
#define QSC 39.6875f /* 127/3.2 quantization scale */
#define DEQ ((3.2f/127.0f)*(3.2f/127.0f)*0.28867513459481287f*1.4426950408889634f)

typedef unsigned int u32;

/* ---------------- global scratch ----------------------------------------- */
__device__ __align__(16) u32   g_qA [8*NB*PA];    /* Q fp16 A-frags (pass2) */
__device__ __align__(16) u32   g_kB [8*NB*PA];    /* K fp16 B-frags (pass2) */
__device__ __align__(16) u32   g_qB8[8*NB*P8];    /* Q int8 B-frags (pass1) */
__device__ __align__(16) u32   g_kA8[8*NB*P8];    /* K int8 A-frags (pass1) */
__device__ __align__(16) u32   g_vw [8*NB*PW];    /* wo·(v/D) fp16 B-frags  */
__device__ __align__(16) float g_v  [8*48*NN];    /* fp32 v */

/* ---------------- helpers ------------------------------------------------ */
__device__ __forceinline__ void mma_h(float* d, uint4 a, uint2 b){
    asm("mma.sync.aligned.m16n8k16.row.col.f32.f16.f16.f32 "
        "{%0,%1,%2,%3},{%4,%5,%6,%7},{%8,%9},{%0,%1,%2,%3};"
        : "+f"(d[0]), "+f"(d[1]), "+f"(d[2]), "+f"(d[3])
        : "r"(a.x), "r"(a.y), "r"(a.z), "r"(a.w), "r"(b.x), "r"(b.y));
}
__device__ __forceinline__ void mma_h16(u32* d, uint4 a, uint2 b){
    asm("mma.sync.aligned.m16n8k16.row.col.f16.f16.f16.f16 "
        "{%0,%1},{%2,%3,%4,%5},{%6,%7},{%0,%1};"
        : "+r"(d[0]), "+r"(d[1])
        : "r"(a.x), "r"(a.y), "r"(a.z), "r"(a.w), "r"(b.x), "r"(b.y));
}
__device__ __forceinline__ void mma_i8(int* d, uint4 a, uint2 b){
    asm("mma.sync.aligned.m16n8k32.row.col.s32.s8.s8.s32 "
        "{%0,%1,%2,%3},{%4,%5,%6,%7},{%8,%9},{%0,%1,%2,%3};"
        : "+r"(d[0]), "+r"(d[1]), "+r"(d[2]), "+r"(d[3])
        : "r"(a.x), "r"(a.y), "r"(a.z), "r"(a.w), "r"(b.x), "r"(b.y));
}
__device__ __forceinline__ u32 pkh(float lo, float hi){
    __half2 h = __floats2half2_rn(lo, hi);
    return *(u32*)&h;
}
__device__ __forceinline__ u32 cvt2h(float lo, float hi){
    u32 r; asm("cvt.rn.f16x2.f32 %0, %1, %2;" : "=r"(r) : "f"(hi), "f"(lo));
    return r;
}
__device__ __forceinline__ u32 ex2h2(u32 x, u32 hmin){
    u32 r;
    asm("{\n\t.reg .b32 t;\n\tmin.f16x2 t, %1, %2;\n\tex2.approx.f16x2 %0, t;\n\t}"
        : "=r"(r) : "r"(x), "r"(hmin));
    return r;
}
__device__ __forceinline__ u32 pk8(float f0, float f1, float f2, float f3){
    const int i0 = __float2int_rn(fminf(fmaxf(f0, -127.f), 127.f));
    const int i1 = __float2int_rn(fminf(fmaxf(f1, -127.f), 127.f));
    const int i2 = __float2int_rn(fminf(fmaxf(f2, -127.f), 127.f));
    const int i3 = __float2int_rn(fminf(fmaxf(f3, -127.f), 127.f));
    return (u32)(i0 & 0xFF) | ((u32)(i1 & 0xFF) << 8)
         | ((u32)(i2 & 0xFF) << 16) | ((u32)(i3 & 0xFF) << 24);
}
__device__ __forceinline__ u32 smem_u32(const void* p){
    u32 a;
    asm("{ .reg .u64 t; cvta.to.shared.u64 t, %1; cvt.u32.u64 %0, t; }" : "=r"(a) : "l"(p));
    return a;
}
__device__ __forceinline__ void cpa16(u32 d, const void* s){
    asm volatile("cp.async.ca.shared.global [%0], [%1], 16;" :: "r"(d), "l"(s));
}
#define CP_COMMIT() asm volatile("cp.async.commit_group;")
#define CP_WAIT1()  asm volatile("cp.async.wait_group 1;")
#define CP_WAIT0()  asm volatile("cp.async.wait_group 0;")
#define HMIN_CONST 0x4BC04BC0u   /* {15.5h, 15.5h} */

/* ========== Kernel A: QKV -> fp16 + int8 panels; 3 warp-groups =========== */
/* dyn smem: stage[10240 u32] + w_s[1296] + b_s[108] = 46576 B
   stage u32 segments: qA fp16 [0,3072) | qB8 [3072,5120) |
                       kA8 [5120,7168) | kB fp16 [7168,10240)              */
__global__ __launch_bounds__(384)
void qkv_kernel(const float* __restrict__ x,
                const float* __restrict__ wq, const float* __restrict__ bq,
                const float* __restrict__ wk, const float* __restrict__ bk,
                const float* __restrict__ wv, const float* __restrict__ bv)
{
    extern __shared__ __align__(16) u32 dynq[];
    u32* stage = dynq;
    float* w_s = (float*)(dynq + 10240);
    float* b_s = w_s + 3*432;

    const int t = threadIdx.x;
    const int wg = t >> 7, tl = t & 127;
    const int b = blockIdx.y, nblk = blockIdx.x;
    const int n = nblk*128 + tl;

    const float* wsrc = (wg == 0) ? wq : (wg == 1) ? wk : wv;
    const float* bsrc = (wg == 0) ? bq : (wg == 1) ? bk : bv;
    for (int i = tl; i < 432; i += 128) w_s[wg*432 + i] = wsrc[i];
    if (tl < 36) b_s[wg*36 + tl] = bsrc[tl];
    __syncthreads();

    float xv[12];
    #pragma unroll
    for (int c = 0; c < 12; ++c) xv[c] = x[(b*12 + c)*NN + n];

    float ov[64];
    #pragma unroll
    for (int o = 36; o < 64; ++o) ov[o] = 0.f;
    const float* w = w_s + wg*432;
    const float* bb = b_s + wg*36;
    #pragma unroll 4
    for (int o = 0; o < 36; ++o){
        float acc = bb[o];
        #pragma unroll
        for (int c = 0; c < 12; ++c) acc += w[o*12 + c]*xv[c];
        ov[o] = acc;
    }

    if (wg == 2){
        #pragma unroll 4
        for (int o = 0; o < 36; ++o) g_v[((long)(b*48+o))*NN + n] = ov[o];
        #pragma unroll
        for (int o = 36; o < 48; ++o) g_v[((long)(b*48+o))*NN + n] = 0.f;
    } else {
        /* int8 pack of raw values (16 u32: [kk][rh][t4]) */
        u32 ipk[16];
        #pragma unroll
        for (int kk = 0; kk < 2; ++kk)
            #pragma unroll
            for (int rh = 0; rh < 2; ++rh)
                #pragma unroll
                for (int t4 = 0; t4 < 4; ++t4){
                    const int cb = kk*32 + rh*16 + t4*4;
                    ipk[kk*8 + rh*4 + t4] = pk8(ov[cb]*QSC, ov[cb+1]*QSC,
                                                ov[cb+2]*QSC, ov[cb+3]*QSC);
                }

        if (wg == 0){
            /* qB8: int8 B-frags */
            u32* sB8 = stage + 3072;
            const int ct = tl >> 3, gB = tl & 7;
            #pragma unroll
            for (int kk = 0; kk < 2; ++kk)
                #pragma unroll
                for (int rh = 0; rh < 2; ++rh)
                    #pragma unroll
                    for (int t4 = 0; t4 < 4; ++t4)
                        sB8[(ct*2 + kk)*64 + (gB*4 + t4)*2 + rh] = ipk[kk*8 + rh*4 + t4];
            /* qA: fp16 A-frags with SCALE2 folded */
            #pragma unroll
            for (int o = 0; o < 36; ++o) ov[o] *= SCALE2;
            u32* sA = stage;
            const int rt = tl >> 4, lr = tl & 15;
            #pragma unroll
            for (int p = 0; p < 24; ++p){
                const int kk = p >> 3, cp = p & 7;
                const int c0 = kk*16 + cp*2;
                const u32 fp = pkh(ov[c0], ov[c0 + 1]);
                const int regA  = ((cp >> 2) << 1) | (lr >> 3);
                const int laneA = ((lr & 7) << 2) | (cp & 3);
                sA[(rt*3 + kk)*128 + laneA*4 + regA] = fp;
            }
        } else {
            /* kA8: int8 A-frags */
            u32* sA8 = stage + 5120;
            const int rt = tl >> 4, lr = tl & 15, g8 = lr & 7, hf = lr >> 3;
            #pragma unroll
            for (int kk = 0; kk < 2; ++kk)
                #pragma unroll
                for (int rh = 0; rh < 2; ++rh)
                    #pragma unroll
                    for (int t4 = 0; t4 < 4; ++t4)
                        sA8[(rt*2 + kk)*128 + (g8*4 + t4)*4 + (rh*2 + hf)] = ipk[kk*8 + rh*4 + t4];
            /* kB: fp16 B-frags (raw) */
            u32* sB = stage + 7168;
            const int ct = tl >> 3, gB = tl & 7;
            #pragma unroll
            for (int p = 0; p < 24; ++p){
                const int kk = p >> 3, cp = p & 7;
                const int c0 = kk*16 + cp*2;
                const u32 fp = pkh(ov[c0], ov[c0 + 1]);
                const int regB  = cp >> 2;
                const int laneB = (gB << 2) | (cp & 3);
                sB[(ct*3 + kk)*64 + laneB*2 + regB] = fp;
            }
        }
    }
    __syncthreads();

    /* coalesced block copy to gmem panels */
    {
        const int pi = b*NB + nblk;
        const uint4* s4 = (const uint4*)stage;
        for (int i = t; i < 2560; i += 384){
            const uint4 v = s4[i];
            if (i < 768)        ((uint4*)g_qA )[pi*768 + i        ] = v;
            else if (i < 1280)  ((uint4*)g_qB8)[pi*512 + (i - 768)] = v;
            else if (i < 1792)  ((uint4*)g_kA8)[pi*512 + (i -1280)] = v;
            else                ((uint4*)g_kB )[pi*768 + (i -1792)] = v;
        }
    }
}

/* ====== Pass 1 (int8): S = K·Q^T -> D[n] -> vw = wo·(v/D) B-frags ======== */
/* 512 thr = 16 warps: wg = w>>2 owns n-rows wg*32..+31 (2 A-tiles);
   h = w&3 owns m-quarter. k32 x2 per tile.                                 */
__global__ __launch_bounds__(512)
void pass1_kernel(const float* __restrict__ wo)
{
    __shared__ __align__(16) u32 qb[3*QBUF];
    __shared__ __align__(16) float Dsh[512];
    __shared__ __align__(16) float invd[128];
    __shared__ __align__(16) float wo_s[432];

    const int t = threadIdx.x, w = t >> 5, lane = t & 31;
    const int wg = w >> 2, h = w & 3;
    const int g = lane >> 2, tg = lane & 3;
    const int b = blockIdx.y, nblk = blockIdx.x;
    const u32 hmin = HMIN_CONST;

    for (int i = t; i < 432; i += 512) wo_s[i] = wo[i];

    /* K int8 A-frags: 2 tiles (n-rows wg*32..+31), 2 k32 steps each */
    uint4 a0f[2], a1f[2];
    {
        const u32* kA = g_kA8 + (b*NB + nblk)*P8;
        #pragma unroll
        for (int kk = 0; kk < 2; ++kk){
            a0f[kk] = *(const uint4*)(kA + ((wg*2 + 0)*2 + kk)*128 + lane*4);
            a1f[kk] = *(const uint4*)(kA + ((wg*2 + 1)*2 + kk)*128 + lane*4);
        }
    }

    const char* qsrc = (const char*)(g_qB8 + (long)b*NB*P8);
    {
        cpa16(smem_u32(qb) + t*16, qsrc + t*16);
        CP_COMMIT();
        cpa16(smem_u32(qb + QBUF) + t*16, qsrc + (long)P8*4 + t*16);
        CP_COMMIT();
    }

    float rs00 = 0.f, rs01 = 0.f, rs10 = 0.f, rs11 = 0.f;
    int buf = 0;

    for (int mc = 0; mc < NB; ++mc){
        CP_WAIT1();
        __syncthreads();
        if (mc + 2 < NB){
            const int nb2 = (buf + 2 >= 3) ? buf - 1 : buf + 2;
            cpa16(smem_u32(qb + nb2*QBUF) + t*16, qsrc + (long)(mc + 2)*P8*4 + t*16);
        }
        CP_COMMIT();

        const u32* cur = qb + buf*QBUF;
        #pragma unroll
        for (int cl = 0; cl < 4; ++cl){
            const int ctb = h*4 + cl;
            const uint2 bq0 = *(const uint2*)(cur + (ctb*2 + 0)*64 + lane*2);
            const uint2 bq1 = *(const uint2*)(cur + (ctb*2 + 1)*64 + lane*2);
            {
                int sd[4] = {0, 0, 0, 0};
                mma_i8(sd, a0f[0], bq0); mma_i8(sd, a0f[1], bq1);
                const float f0 = (float)sd[0]*DEQ, f1 = (float)sd[1]*DEQ;
                const float f2 = (float)sd[2]*DEQ, f3 = (float)sd[3]*DEQ;
                const u32 ea = ex2h2(cvt2h(f0, f1), hmin);
                const u32 eb = ex2h2(cvt2h(f2, f3), hmin);
                const float2 fa = __half22float2(*(const __half2*)&ea);
                const float2 fb = __half22float2(*(const __half2*)&eb);
                rs00 += fa.x + fa.y;
                rs01 += fb.x + fb.y;
            }
            {
                int sd[4] = {0, 0, 0, 0};
                mma_i8(sd, a1f[0], bq0); mma_i8(sd, a1f[1], bq1);
                const float f0 = (float)sd[0]*DEQ, f1 = (float)sd[1]*DEQ;
                const float f2 = (float)sd[2]*DEQ, f3 = (float)sd[3]*DEQ;
                const u32 ea = ex2h2(cvt2h(f0, f1), hmin);
                const u32 eb = ex2h2(cvt2h(f2, f3), hmin);
                const float2 fa = __half22float2(*(const __half2*)&ea);
                const float2 fb = __half22float2(*(const __half2*)&eb);
                rs10 += fa.x + fa.y;
                rs11 += fb.x + fb.y;
            }
        }
        buf = (buf + 1 >= 3) ? 0 : buf + 1;
    }

    /* reduce over m-col lanes (tg); stage per-quarter */
    rs00 += __shfl_xor_sync(0xFFFFFFFFu, rs00, 1);
    rs00 += __shfl_xor_sync(0xFFFFFFFFu, rs00, 2);
    rs01 += __shfl_xor_sync(0xFFFFFFFFu, rs01, 1);
    rs01 += __shfl_xor_sync(0xFFFFFFFFu, rs01, 2);
    rs10 += __shfl_xor_sync(0xFFFFFFFFu, rs10, 1);
    rs10 += __shfl_xor_sync(0xFFFFFFFFu, rs10, 2);
    rs11 += __shfl_xor_sync(0xFFFFFFFFu, rs11, 1);
    rs11 += __shfl_xor_sync(0xFFFFFFFFu, rs11, 2);
    if (tg == 0){
        Dsh[h*128 + wg*32 + g]      = rs00;
        Dsh[h*128 + wg*32 + 8 + g]  = rs01;
        Dsh[h*128 + wg*32 + 16 + g] = rs10;
        Dsh[h*128 + wg*32 + 24 + g] = rs11;
    }
    __syncthreads();
    if (t < 128) invd[t] = 1.0f / (Dsh[t] + Dsh[128 + t] + Dsh[256 + t] + Dsh[384 + t]);
    CP_WAIT0();
    __syncthreads();

    /* ---- vw = wo · (v/D): stage v, compute, write B-frag panel ---- */
    float* vstage = (float*)qb;              /* 4608 floats */
    float* vw_s   = vstage + 36*128;         /* 2048 floats (fits 3*QBUF=6912) */
    {
        const float* vb = g_v + (long)b*48*NN + nblk*128;
        for (int idx = t; idx < 36*128; idx += 512){
            const int c = idx >> 7, nn = idx & 127;
            vstage[idx] = vb[(long)c*NN + nn];
        }
    }
    __syncthreads();
    for (int idx = t; idx < 2048; idx += 512){
        const int o = idx >> 7, nn = idx & 127;
        float s = 0.f;
        if (o < 12){
            const float* wrow = wo_s + o*36;
            #pragma unroll 4
            for (int c = 0; c < 36; ++c) s += wrow[c]*vstage[c*128 + nn];
            s *= invd[nn];
        }
        vw_s[idx] = s;
    }
    __syncthreads();
    {
        u32* vdst = g_vw + (b*NB + nblk)*PW;
        for (int j = t; j < PW; j += 512){
            const int reg = j & 1, l5 = (j >> 1) & 31, tile = j >> 6;
            const int kk = tile >> 1, ct = tile & 1;
            const int o = ct*8 + (l5 >> 2);
            const int nn = kk*16 + (l5 & 3)*2 + reg*8;
            vdst[j] = pkh(vw_s[o*128 + nn], vw_s[o*128 + nn + 1]);
        }
    }
}

/* ====== Pass 2 (fp16): S (f16 accum) -> P -> P·vw^T = out ================ */
__global__ __launch_bounds__(512)
void pass2_kernel(const float* __restrict__ bo, float* __restrict__ out)
{
    extern __shared__ __align__(16) char smraw[];
    u32* sK  = (u32*)smraw;                 /* [3][3072] u32 */
    u32* sW  = sK + 3*PA;                   /* [3][1024] u32 */
    float* bo_s = (float*)(sW + 3*PW);      /* 16 floats */
    float* outb = (float*)smraw;            /* 16*132 floats, reuse after loop */

    const int t = threadIdx.x, w = t >> 5, lane = t & 31;
    const int wg = w >> 2, h = w & 3;
    const int g = lane >> 2, tg = lane & 3;
    const int b = blockIdx.y, mt = blockIdx.x;
    const u32 hmin = HMIN_CONST;

    if (t < 12) bo_s[t] = bo[t];

    uint4 aq0[3], aq1[3];
    {
        const u32* qA = g_qA + (b*NB + mt)*PA;
        #pragma unroll
        for (int ck = 0; ck < 3; ++ck){
            aq0[ck] = *(const uint4*)(qA + ((wg*2 + 0)*3 + ck)*128 + lane*4);
            aq1[ck] = *(const uint4*)(qA + ((wg*2 + 1)*3 + ck)*128 + lane*4);
        }
    }

    const char* ksrc = (const char*)(g_kB + (long)b*NB*PA);
    const char* wsrc = (const char*)(g_vw + (long)b*NB*PW);
    {
        const u32 dk0 = smem_u32(sK), dw0 = smem_u32(sW);
        for (int i = t; i < 768; i += 512) cpa16(dk0 + i*16, ksrc + i*16);
        if (t < 256) cpa16(dw0 + t*16, wsrc + t*16);
        CP_COMMIT();
        const u32 dk1 = smem_u32(sK + PA), dw1 = smem_u32(sW + PW);
        const char* sk1 = ksrc + (long)PA*4;
        const char* sw1 = wsrc + (long)PW*4;
        for (int i = t; i < 768; i += 512) cpa16(dk1 + i*16, sk1 + i*16);
        if (t < 256) cpa16(dw1 + t*16, sw1 + t*16);
        CP_COMMIT();
    }

    float accA[2][4], accB[2][4];
    #pragma unroll
    for (int ct = 0; ct < 2; ++ct)
        #pragma unroll
        for (int i = 0; i < 4; ++i){ accA[ct][i] = 0.f; accB[ct][i] = 0.f; }

    int buf = 0;

    for (int nc = 0; nc < NB; ++nc){
        CP_WAIT1();
        __syncthreads();
        if (nc + 2 < NB){
            const int nb2 = (buf + 2 >= 3) ? buf - 1 : buf + 2;
            const u32 dk = smem_u32(sK + nb2*PA);
            const u32 dw = smem_u32(sW + nb2*PW);
            const char* sk = ksrc + (long)(nc + 2)*PA*4;
            const char* sw = wsrc + (long)(nc + 2)*PW*4;
            for (int i = t; i < 768; i += 512) cpa16(dk + i*16, sk + i*16);
            if (t < 256) cpa16(dw + t*16, sw + t*16);
        }
        CP_COMMIT();

        const u32* curK = sK + buf*PA;
        const u32* curW = sW + buf*PW;

        #pragma unroll
        for (int jj = 0; jj < 2; ++jj){
            const int kk = h*2 + jj;
            const int ctb0 = 2*kk, ctb1 = 2*kk + 1;
            uint2 b00 = *(const uint2*)(curK + (ctb0*3 + 0)*64 + lane*2);
            uint2 b01 = *(const uint2*)(curK + (ctb0*3 + 1)*64 + lane*2);
            uint2 b02 = *(const uint2*)(curK + (ctb0*3 + 2)*64 + lane*2);
            uint2 b10 = *(const uint2*)(curK + (ctb1*3 + 0)*64 + lane*2);
            uint2 b11 = *(const uint2*)(curK + (ctb1*3 + 1)*64 + lane*2);
            uint2 b12 = *(const uint2*)(curK + (ctb1*3 + 2)*64 + lane*2);
            uint2 bw0 = *(const uint2*)(curW + (kk*2 + 0)*64 + lane*2);
            uint2 bw1 = *(const uint2*)(curW + (kk*2 + 1)*64 + lane*2);

            {
                u32 s0[2] = {0u, 0u}, s1[2] = {0u, 0u};
                mma_h16(s0, aq0[0], b00); mma_h16(s0, aq0[1], b01); mma_h16(s0, aq0[2], b02);
                mma_h16(s1, aq0[0], b10); mma_h16(s1, aq0[1], b11); mma_h16(s1, aq0[2], b12);
                uint4 pf;
                pf.x = ex2h2(s0[0], hmin);
                pf.y = ex2h2(s0[1], hmin);
                pf.z = ex2h2(s1[0], hmin);
                pf.w = ex2h2(s1[1], hmin);
                mma_h(accA[0], pf, bw0);
                mma_h(accA[1], pf, bw1);
            }
            {
                u32 s0[2] = {0u, 0u}, s1[2] = {0u, 0u};
                mma_h16(s0, aq1[0], b00); mma_h16(s0, aq1[1], b01); mma_h16(s0, aq1[2], b02);
                mma_h16(s1, aq1[0], b10); mma_h16(s1, aq1[1], b11); mma_h16(s1, aq1[2], b12);
                uint4 pf;
                pf.x = ex2h2(s0[0], hmin);
                pf.y = ex2h2(s0[1], hmin);
                pf.z = ex2h2(s1[0], hmin);
                pf.w = ex2h2(s1[1], hmin);
                mma_h(accB[0], pf, bw0);
                mma_h(accB[1], pf, bw1);
            }
        }
        buf = (buf + 1 >= 3) ? 0 : buf + 1;
    }

    CP_WAIT0();
    __syncthreads();
    #pragma unroll
    for (int ph = 0; ph < 4; ++ph){
        if (h == ph){
            #pragma unroll
            for (int ct = 0; ct < 2; ++ct){
                const int mA = wg*32 + g, mB = mA + 16, cb = ct*8 + 2*tg;
                if (ph == 0){
                    outb[cb*132 + mA]           = accA[ct][0];
                    outb[(cb + 1)*132 + mA]     = accA[ct][1];
                    outb[cb*132 + mA + 8]       = accA[ct][2];
                    outb[(cb + 1)*132 + mA + 8] = accA[ct][3];
                    outb[cb*132 + mB]           = accB[ct][0];
                    outb[(cb + 1)*132 + mB]     = accB[ct][1];
                    outb[cb*132 + mB + 8]       = accB[ct][2];
                    outb[(cb + 1)*132 + mB + 8] = accB[ct][3];
                } else {
                    outb[cb*132 + mA]           += accA[ct][0];
                    outb[(cb + 1)*132 + mA]     += accA[ct][1];
                    outb[cb*132 + mA + 8]       += accA[ct][2];
                    outb[(cb + 1)*132 + mA + 8] += accA[ct][3];
                    outb[cb*132 + mB]           += accB[ct][0];
                    outb[(cb + 1)*132 + mB]     += accB[ct][1];
                    outb[cb*132 + mB + 8]       += accB[ct][2];
                    outb[(cb + 1)*132 + mB + 8] += accB[ct][3];
                }
            }
        }
        __syncthreads();
    }

    {
        const int og = t >> 7, m = t & 127;
        #pragma unroll
        for (int oo = 0; oo < 3; ++oo){
            const int o = og*3 + oo;
            out[((long)(b*12 + o))*NN + mt*128 + m] = outb[o*132 + m] + bo_s[o];
        }
    }
}

/* ============================== launch =================================== */
extern "C" void kernel_launch(void* const* d_in, const int* in_sizes, int n_in,
                              void* d_out, int out_size)
{
    const float* x  = (const float*)d_in[0];
    const float* wq = (const float*)d_in[1];
    const float* bq = (const float*)d_in[2];
    const float* wk = (const float*)d_in[3];
    const float* bk = (const float*)d_in[4];
    const float* wv = (const float*)d_in[5];
    const float* bv = (const float*)d_in[6];
    const float* wo = (const float*)d_in[7];
    const float* bo = (const float*)d_in[8];
    float* out = (float*)d_out;

    /* qkv: 10240*4 + 1296*4 + 108*4 = 46576 */
    cudaFuncSetAttribute(qkv_kernel,
                         cudaFuncAttributeMaxDynamicSharedMemorySize, 46576);
    /* pass2: 3*PA*4 + 3*PW*4 + 64 = 49216 */
    cudaFuncSetAttribute(pass2_kernel,
                         cudaFuncAttributeMaxDynamicSharedMemorySize, 49216);

    qkv_kernel  <<<dim3(NB, 8), 384, 46576>>>(x, wq, bq, wk, bk, wv, bv);
    pass1_kernel<<<dim3(NB, 8), 512>>>(wo);
    pass2_kernel<<<dim3(NB, 8), 512, 49216>>>(bo, out);
}

// round 15
// speedup vs baseline: 1.7395x; 1.7395x over previous
#include <cuda_runtime.h>
#include <cuda_fp16.h>
#include <cstdint>

#define NN 4096
#define NB 32
#define PA 3072      /* u32 per fragment panel: 128 rows/cols x 48 k fp16 pairs */
#define PW 1024      /* u32 per vw B-frag panel: 16 ch x 128 n fp16 */
#define SCALE2 (0.28867513459481287f * 1.4426950408889634f)  /* (1/sqrt12)*log2e */

typedef unsigned int u32;

/* ---------------- global scratch ----------------------------------------- */
__device__ __align__(16) u32   g_qA[8*NB*PA];     /* Q fp16 A-frags (pass2) */
__device__ __align__(16) u32   g_qB[8*NB*PA];     /* Q fp16 B-frags (pass1) */
__device__ __align__(16) u32   g_kA[8*NB*PA];     /* K fp16 A-frags (pass1) */
__device__ __align__(16) u32   g_kB[8*NB*PA];     /* K fp16 B-frags (pass2) */
__device__ __align__(16) u32   g_vw[8*NB*PW];     /* wo·(v/D) fp16 B-frags  */
__device__ __align__(16) float g_v [8*48*NN];     /* fp32 v (rows 0..35 used) */

/* ---------------- helpers ------------------------------------------------ */
__device__ __forceinline__ void mma_h(float* d, uint4 a, uint2 b){
    asm("mma.sync.aligned.m16n8k16.row.col.f32.f16.f16.f32 "
        "{%0,%1,%2,%3},{%4,%5,%6,%7},{%8,%9},{%0,%1,%2,%3};"
        : "+f"(d[0]), "+f"(d[1]), "+f"(d[2]), "+f"(d[3])
        : "r"(a.x), "r"(a.y), "r"(a.z), "r"(a.w), "r"(b.x), "r"(b.y));
}
__device__ __forceinline__ void mma_h16(u32* d, uint4 a, uint2 b){
    asm("mma.sync.aligned.m16n8k16.row.col.f16.f16.f16.f16 "
        "{%0,%1},{%2,%3,%4,%5},{%6,%7},{%0,%1};"
        : "+r"(d[0]), "+r"(d[1])
        : "r"(a.x), "r"(a.y), "r"(a.z), "r"(a.w), "r"(b.x), "r"(b.y));
}
__device__ __forceinline__ u32 pkh(float lo, float hi){
    __half2 h = __floats2half2_rn(lo, hi);
    return *(u32*)&h;
}
__device__ __forceinline__ u32 ex2h2(u32 x, u32 hmin){
    u32 r;
    asm("{\n\t.reg .b32 t;\n\tmin.f16x2 t, %1, %2;\n\tex2.approx.f16x2 %0, t;\n\t}"
        : "=r"(r) : "r"(x), "r"(hmin));
    return r;
}
__device__ __forceinline__ u32 smem_u32(const void* p){
    u32 a;
    asm("{ .reg .u64 t; cvta.to.shared.u64 t, %1; cvt.u32.u64 %0, t; }" : "=r"(a) : "l"(p));
    return a;
}
__device__ __forceinline__ void cpa16(u32 d, const void* s){
    asm volatile("cp.async.ca.shared.global [%0], [%1], 16;" :: "r"(d), "l"(s));
}
#define CP_COMMIT() asm volatile("cp.async.commit_group;")
#define CP_WAIT1()  asm volatile("cp.async.wait_group 1;")
#define CP_WAIT0()  asm volatile("cp.async.wait_group 0;")
#define HMIN_CONST 0x4BC04BC0u   /* {15.5h, 15.5h} */

/* ========== Kernel A: QKV -> panels; 6 half-warpgroups (q|k|v x 2) ======= */
/* dyn smem: stage[12288 u32] | w_s[1296 f] | b_s[108 f] = 54768 B          */
__global__ __launch_bounds__(768)
void qkv_kernel(const float* __restrict__ x,
                const float* __restrict__ wq, const float* __restrict__ bq,
                const float* __restrict__ wk, const float* __restrict__ bk,
                const float* __restrict__ wv, const float* __restrict__ bv)
{
    extern __shared__ __align__(16) u32 dynq[];
    u32* stage = dynq;                       /* 12288 u32 = 48KB */
    float* w_s = (float*)(dynq + 12288);     /* 3*432 */
    float* b_s = w_s + 3*432;                /* 3*36  */

    const int t = threadIdx.x;
    const int hw = t >> 7, tl = t & 127;
    const int kind = hw >> 1, half = hw & 1;   /* kind: 0=q 1=k 2=v */
    const int b = blockIdx.y, nblk = blockIdx.x;
    const int n = nblk*128 + tl;

    const float* wsrc = (kind == 0) ? wq : (kind == 1) ? wk : wv;
    const float* bsrc = (kind == 0) ? bq : (kind == 1) ? bk : bv;
    for (int i = tl + half*128; i < 432; i += 256) w_s[kind*432 + i] = wsrc[i];
    if (half == 0 && tl < 36) b_s[kind*36 + tl] = bsrc[tl];
    __syncthreads();

    float xv[12];
    #pragma unroll
    for (int c = 0; c < 12; ++c) xv[c] = x[(b*12 + c)*NN + n];

    /* this half computes channels [half*18, half*18+18) */
    const int o0 = half*18;
    float ov[18];
    {
        const float* w = w_s + kind*432;
        const float* bb = b_s + kind*36;
        #pragma unroll 3
        for (int oo = 0; oo < 18; ++oo){
            const int o = o0 + oo;
            float acc = bb[o];
            #pragma unroll
            for (int c = 0; c < 12; ++c) acc += w[o*12 + c]*xv[c];
            ov[oo] = acc;
        }
    }

    if (kind == 2){
        #pragma unroll 3
        for (int oo = 0; oo < 18; ++oo)
            g_v[((long)(b*48 + o0 + oo))*NN + n] = ov[oo];
    } else {
        if (kind == 0){
            #pragma unroll
            for (int oo = 0; oo < 18; ++oo) ov[oo] *= SCALE2;  /* fold scale+log2e */
        }
        /* scatter into smem stage: [qA|qB|kA|kB], 3072 u32 each */
        u32* sA = stage + kind*6144;
        u32* sB = sA + 3072;
        const int rt = tl >> 4, lr = tl & 15;
        const int ct = tl >> 3, gB = tl & 7;
        #pragma unroll
        for (int p = 0; p < 24; ++p){
            const int kk = p >> 3, cp = p & 7;
            const int c0 = kk*16 + cp*2;
            /* ownership: half0 -> c0 in [0,18); half1 -> c0 >= 18 (incl. zero pad) */
            const bool own = half ? (c0 >= 18) : (c0 < 18);
            if (!own) continue;
            const int oo = c0 - o0;
            const float f0 = (c0 < 36) ? ov[oo] : 0.f;
            const float f1 = (c0 + 1 < 36) ? ov[oo + 1] : 0.f;
            const u32 fp = pkh(f0, f1);
            const int regA  = ((cp >> 2) << 1) | (lr >> 3);
            const int laneA = ((lr & 7) << 2) | (cp & 3);
            sA[(rt*3 + kk)*128 + laneA*4 + regA] = fp;
            const int regB  = cp >> 2;
            const int laneB = (gB << 2) | (cp & 3);
            sB[(ct*3 + kk)*64 + laneB*2 + regB] = fp;
        }
    }
    __syncthreads();

    /* coalesced block copy: 3072 uint4 -> 4 gmem panels */
    {
        const int base4 = ((b*NB + nblk)*PA) >> 2;
        const uint4* s4 = (const uint4*)stage;
        for (int i = t; i < 3072; i += 768){
            const int seg = i/768, off = i - seg*768;
            uint4* dst = (seg == 0) ? (uint4*)g_qA : (seg == 1) ? (uint4*)g_qB
                       : (seg == 2) ? (uint4*)g_kA : (uint4*)g_kB;
            dst[base4 + off] = s4[i];
        }
    }
}

/* ====== Pass 1: S = K·Q^T (f16 accum) -> D[n] -> vw = wo·(v/D) =========== */
__global__ __launch_bounds__(512)
void pass1_kernel(const float* __restrict__ wo)
{
    __shared__ __align__(16) u32 qb[3][PA];
    __shared__ __align__(16) float Dsh[512];
    __shared__ __align__(16) float invd[128];
    __shared__ __align__(16) float wo_s[432];

    const int t = threadIdx.x, w = t >> 5, lane = t & 31;
    const int wg = w >> 2, h = w & 3;
    const int g = lane >> 2, tg = lane & 3;
    const int b = blockIdx.y, nblk = blockIdx.x;
    const u32 hmin = HMIN_CONST;

    for (int i = t; i < 432; i += 512) wo_s[i] = wo[i];

    uint4 a0f[3], a1f[3];
    {
        const u32* kA = g_kA + (b*NB + nblk)*PA;
        #pragma unroll
        for (int ck = 0; ck < 3; ++ck){
            a0f[ck] = *(const uint4*)(kA + ((wg*2 + 0)*3 + ck)*128 + lane*4);
            a1f[ck] = *(const uint4*)(kA + ((wg*2 + 1)*3 + ck)*128 + lane*4);
        }
    }

    const char* qsrc = (const char*)(g_qB + (long)b*NB*PA);
    {
        const u32 d0 = smem_u32(&qb[0][0]);
        for (int i = t; i < 768; i += 512) cpa16(d0 + i*16, qsrc + i*16);
        CP_COMMIT();
        const u32 d1 = smem_u32(&qb[1][0]);
        const char* s1 = qsrc + (long)PA*4;
        for (int i = t; i < 768; i += 512) cpa16(d1 + i*16, s1 + i*16);
        CP_COMMIT();
    }

    float rs00 = 0.f, rs01 = 0.f, rs10 = 0.f, rs11 = 0.f;
    int buf = 0;

    for (int mc = 0; mc < NB; ++mc){
        CP_WAIT1();
        __syncthreads();
        if (mc + 2 < NB){
            const int nb2 = (buf + 2 >= 3) ? buf - 1 : buf + 2;
            const u32 d = smem_u32(&qb[nb2][0]);
            const char* s = qsrc + (long)(mc + 2)*PA*4;
            for (int i = t; i < 768; i += 512) cpa16(d + i*16, s + i*16);
        }
        CP_COMMIT();

        const u32* cur = &qb[buf][0];
        #pragma unroll
        for (int cl = 0; cl < 4; ++cl){
            const int ctb = h*4 + cl;
            uint2 bq0 = *(const uint2*)(cur + (ctb*3 + 0)*64 + lane*2);
            uint2 bq1 = *(const uint2*)(cur + (ctb*3 + 1)*64 + lane*2);
            uint2 bq2 = *(const uint2*)(cur + (ctb*3 + 2)*64 + lane*2);
            {
                u32 s[2] = {0u, 0u};
                mma_h16(s, a0f[0], bq0); mma_h16(s, a0f[1], bq1); mma_h16(s, a0f[2], bq2);
                const u32 ea = ex2h2(s[0], hmin);
                const u32 eb = ex2h2(s[1], hmin);
                const float2 fa = __half22float2(*(const __half2*)&ea);
                const float2 fb = __half22float2(*(const __half2*)&eb);
                rs00 += fa.x + fa.y;
                rs01 += fb.x + fb.y;
            }
            {
                u32 s[2] = {0u, 0u};
                mma_h16(s, a1f[0], bq0); mma_h16(s, a1f[1], bq1); mma_h16(s, a1f[2], bq2);
                const u32 ea = ex2h2(s[0], hmin);
                const u32 eb = ex2h2(s[1], hmin);
                const float2 fa = __half22float2(*(const __half2*)&ea);
                const float2 fb = __half22float2(*(const __half2*)&eb);
                rs10 += fa.x + fa.y;
                rs11 += fb.x + fb.y;
            }
        }
        buf = (buf + 1 >= 3) ? 0 : buf + 1;
    }

    rs00 += __shfl_xor_sync(0xFFFFFFFFu, rs00, 1);
    rs00 += __shfl_xor_sync(0xFFFFFFFFu, rs00, 2);
    rs01 += __shfl_xor_sync(0xFFFFFFFFu, rs01, 1);
    rs01 += __shfl_xor_sync(0xFFFFFFFFu, rs01, 2);
    rs10 += __shfl_xor_sync(0xFFFFFFFFu, rs10, 1);
    rs10 += __shfl_xor_sync(0xFFFFFFFFu, rs10, 2);
    rs11 += __shfl_xor_sync(0xFFFFFFFFu, rs11, 1);
    rs11 += __shfl_xor_sync(0xFFFFFFFFu, rs11, 2);
    if (tg == 0){
        Dsh[h*128 + wg*32 + g]      = rs00;
        Dsh[h*128 + wg*32 + 8 + g]  = rs01;
        Dsh[h*128 + wg*32 + 16 + g] = rs10;
        Dsh[h*128 + wg*32 + 24 + g] = rs11;
    }
    __syncthreads();
    if (t < 128) invd[t] = 1.0f / (Dsh[t] + Dsh[128 + t] + Dsh[256 + t] + Dsh[384 + t]);
    CP_WAIT0();
    __syncthreads();

    /* ---- vw = wo · (v/D): stage v, compute, write B-frag panel ---- */
    float* vstage = (float*)&qb[0][0];       /* 36*128 floats */
    float* vw_s   = vstage + 36*128;         /* 16*128 floats */
    {
        const float* vb = g_v + (long)b*48*NN + nblk*128;
        for (int idx = t; idx < 36*128; idx += 512){
            const int c = idx >> 7, nn = idx & 127;
            vstage[idx] = vb[(long)c*NN + nn];
        }
    }
    __syncthreads();
    for (int idx = t; idx < 2048; idx += 512){
        const int o = idx >> 7, nn = idx & 127;
        float s = 0.f;
        if (o < 12){
            const float* wrow = wo_s + o*36;
            #pragma unroll 4
            for (int c = 0; c < 36; ++c) s += wrow[c]*vstage[c*128 + nn];
            s *= invd[nn];
        }
        vw_s[idx] = s;
    }
    __syncthreads();
    {
        u32* vdst = g_vw + (b*NB + nblk)*PW;
        for (int j = t; j < PW; j += 512){
            const int reg = j & 1, l5 = (j >> 1) & 31, tile = j >> 6;
            const int kk = tile >> 1, ct = tile & 1;
            const int o = ct*8 + (l5 >> 2);
            const int nn = kk*16 + (l5 & 3)*2 + reg*8;
            vdst[j] = pkh(vw_s[o*128 + nn], vw_s[o*128 + nn + 1]);
        }
    }
}

/* ====== Pass 2: S (f16 accum) -> P -> P·vw^T (f32 accum) = out =========== */
__global__ __launch_bounds__(512)
void pass2_kernel(const float* __restrict__ bo, float* __restrict__ out)
{
    extern __shared__ __align__(16) char smraw[];
    u32* sK  = (u32*)smraw;                 /* [3][3072] u32 */
    u32* sW  = sK + 3*PA;                   /* [3][1024] u32 */
    float* bo_s = (float*)(sW + 3*PW);      /* 16 floats */
    float* outb = (float*)smraw;            /* 16*132 floats, reuse after loop */

    const int t = threadIdx.x, w = t >> 5, lane = t & 31;
    const int wg = w >> 2, h = w & 3;
    const int g = lane >> 2, tg = lane & 3;
    const int b = blockIdx.y, mt = blockIdx.x;
    const u32 hmin = HMIN_CONST;

    if (t < 12) bo_s[t] = bo[t];

    uint4 aq0[3], aq1[3];
    {
        const u32* qA = g_qA + (b*NB + mt)*PA;
        #pragma unroll
        for (int ck = 0; ck < 3; ++ck){
            aq0[ck] = *(const uint4*)(qA + ((wg*2 + 0)*3 + ck)*128 + lane*4);
            aq1[ck] = *(const uint4*)(qA + ((wg*2 + 1)*3 + ck)*128 + lane*4);
        }
    }

    const char* ksrc = (const char*)(g_kB + (long)b*NB*PA);
    const char* wsrc = (const char*)(g_vw + (long)b*NB*PW);
    {
        const u32 dk0 = smem_u32(sK), dw0 = smem_u32(sW);
        for (int i = t; i < 768; i += 512) cpa16(dk0 + i*16, ksrc + i*16);
        if (t < 256) cpa16(dw0 + t*16, wsrc + t*16);
        CP_COMMIT();
        const u32 dk1 = smem_u32(sK + PA), dw1 = smem_u32(sW + PW);
        const char* sk1 = ksrc + (long)PA*4;
        const char* sw1 = wsrc + (long)PW*4;
        for (int i = t; i < 768; i += 512) cpa16(dk1 + i*16, sk1 + i*16);
        if (t < 256) cpa16(dw1 + t*16, sw1 + t*16);
        CP_COMMIT();
    }

    float accA[2][4], accB[2][4];
    #pragma unroll
    for (int ct = 0; ct < 2; ++ct)
        #pragma unroll
        for (int i = 0; i < 4; ++i){ accA[ct][i] = 0.f; accB[ct][i] = 0.f; }

    int buf = 0;

    for (int nc = 0; nc < NB; ++nc){
        CP_WAIT1();
        __syncthreads();
        if (nc + 2 < NB){
            const int nb2 = (buf + 2 >= 3) ? buf - 1 : buf + 2;
            const u32 dk = smem_u32(sK + nb2*PA);
            const u32 dw = smem_u32(sW + nb2*PW);
            const char* sk = ksrc + (long)(nc + 2)*PA*4;
            const char* sw = wsrc + (long)(nc + 2)*PW*4;
            for (int i = t; i < 768; i += 512) cpa16(dk + i*16, sk + i*16);
            if (t < 256) cpa16(dw + t*16, sw + t*16);
        }
        CP_COMMIT();

        const u32* curK = sK + buf*PA;
        const u32* curW = sW + buf*PW;

        #pragma unroll
        for (int jj = 0; jj < 2; ++jj){
            const int kk = h*2 + jj;
            const int ctb0 = 2*kk, ctb1 = 2*kk + 1;
            uint2 b00 = *(const uint2*)(curK + (ctb0*3 + 0)*64 + lane*2);
            uint2 b01 = *(const uint2*)(curK + (ctb0*3 + 1)*64 + lane*2);
            uint2 b02 = *(const uint2*)(curK + (ctb0*3 + 2)*64 + lane*2);
            uint2 b10 = *(const uint2*)(curK + (ctb1*3 + 0)*64 + lane*2);
            uint2 b11 = *(const uint2*)(curK + (ctb1*3 + 1)*64 + lane*2);
            uint2 b12 = *(const uint2*)(curK + (ctb1*3 + 2)*64 + lane*2);
            uint2 bw0 = *(const uint2*)(curW + (kk*2 + 0)*64 + lane*2);
            uint2 bw1 = *(const uint2*)(curW + (kk*2 + 1)*64 + lane*2);

            {
                u32 s0[2] = {0u, 0u}, s1[2] = {0u, 0u};
                mma_h16(s0, aq0[0], b00); mma_h16(s0, aq0[1], b01); mma_h16(s0, aq0[2], b02);
                mma_h16(s1, aq0[0], b10); mma_h16(s1, aq0[1], b11); mma_h16(s1, aq0[2], b12);
                uint4 pf;
                pf.x = ex2h2(s0[0], hmin);
                pf.y = ex2h2(s0[1], hmin);
                pf.z = ex2h2(s1[0], hmin);
                pf.w = ex2h2(s1[1], hmin);
                mma_h(accA[0], pf, bw0);
                mma_h(accA[1], pf, bw1);
            }
            {
                u32 s0[2] = {0u, 0u}, s1[2] = {0u, 0u};
                mma_h16(s0, aq1[0], b00); mma_h16(s0, aq1[1], b01); mma_h16(s0, aq1[2], b02);
                mma_h16(s1, aq1[0], b10); mma_h16(s1, aq1[1], b11); mma_h16(s1, aq1[2], b12);
                uint4 pf;
                pf.x = ex2h2(s0[0], hmin);
                pf.y = ex2h2(s0[1], hmin);
                pf.z = ex2h2(s1[0], hmin);
                pf.w = ex2h2(s1[1], hmin);
                mma_h(accB[0], pf, bw0);
                mma_h(accB[1], pf, bw1);
            }
        }
        buf = (buf + 1 >= 3) ? 0 : buf + 1;
    }

    CP_WAIT0();
    __syncthreads();
    #pragma unroll
    for (int ph = 0; ph < 4; ++ph){
        if (h == ph){
            #pragma unroll
            for (int ct = 0; ct < 2; ++ct){
                const int mA = wg*32 + g, mB = mA + 16, cb = ct*8 + 2*tg;
                if (ph == 0){
                    outb[cb*132 + mA]           = accA[ct][0];
                    outb[(cb + 1)*132 + mA]     = accA[ct][1];
                    outb[cb*132 + mA + 8]       = accA[ct][2];
                    outb[(cb + 1)*132 + mA + 8] = accA[ct][3];
                    outb[cb*132 + mB]           = accB[ct][0];
                    outb[(cb + 1)*132 + mB]     = accB[ct][1];
                    outb[cb*132 + mB + 8]       = accB[ct][2];
                    outb[(cb + 1)*132 + mB + 8] = accB[ct][3];
                } else {
                    outb[cb*132 + mA]           += accA[ct][0];
                    outb[(cb + 1)*132 + mA]     += accA[ct][1];
                    outb[cb*132 + mA + 8]       += accA[ct][2];
                    outb[(cb + 1)*132 + mA + 8] += accA[ct][3];
                    outb[cb*132 + mB]           += accB[ct][0];
                    outb[(cb + 1)*132 + mB]     += accB[ct][1];
                    outb[cb*132 + mB + 8]       += accB[ct][2];
                    outb[(cb + 1)*132 + mB + 8] += accB[ct][3];
                }
            }
        }
        __syncthreads();
    }

    {
        const int og = t >> 7, m = t & 127;
        #pragma unroll
        for (int oo = 0; oo < 3; ++oo){
            const int o = og*3 + oo;
            out[((long)(b*12 + o))*NN + mt*128 + m] = outb[o*132 + m] + bo_s[o];
        }
    }
}

/* ============================== launch =================================== */
extern "C" void kernel_launch(void* const* d_in, const int* in_sizes, int n_in,
                              void* d_out, int out_size)
{
    const float* x  = (const float*)d_in[0];
    const float* wq = (const float*)d_in[1];
    const float* bq = (const float*)d_in[2];
    const float* wk = (const float*)d_in[3];
    const float* bk = (const float*)d_in[4];
    const float* wv = (const float*)d_in[5];
    const float* bv = (const float*)d_in[6];
    const float* wo = (const float*)d_in[7];
    const float* bo = (const float*)d_in[8];
    float* out = (float*)d_out;

    /* qkv dyn smem: 12288*4 + 1296*4 + 108*4 = 54768 */
    cudaFuncSetAttribute(qkv_kernel,
                         cudaFuncAttributeMaxDynamicSharedMemorySize, 54768);
    /* pass2 dyn smem: 3*PA*4 + 3*PW*4 + 64 = 49216 */
    cudaFuncSetAttribute(pass2_kernel,
                         cudaFuncAttributeMaxDynamicSharedMemorySize, 49216);

    qkv_kernel  <<<dim3(NB, 8), 768, 54768>>>(x, wq, bq, wk, bk, wv, bv);
    pass1_kernel<<<dim3(NB, 8), 512>>>(wo);
    pass2_kernel<<<dim3(NB, 8), 512, 49216>>>(bo, out);
}

// round 16
// speedup vs baseline: 2.7910x; 1.6045x over previous
#include <cuda_runtime.h>
#include <cuda_fp16.h>
#include <cstdint>

#define NN 4096
#define NB 32
#define P16 1024     /* u32 per 16-k fragment panel (128 rows/cols) */
#define PW 1024      /* u32 per vw B-frag panel */
#define SCALE2 (0.28867513459481287f * 1.4426950408889634f)  /* (1/sqrt12)*log2e */

typedef unsigned int u32;

/* ---------------- global scratch ----------------------------------------- */
__device__ __align__(16) u32   g_xA[8*NB*P16];    /* x~ A-frags (pass2 rows) */
__device__ __align__(16) u32   g_xB[8*NB*P16];    /* x~ B-frags (pass1 cols) */
__device__ __align__(16) u32   g_yA[8*NB*P16];    /* y~ A-frags (pass1 rows) */
__device__ __align__(16) u32   g_yB[8*NB*P16];    /* y~ B-frags (pass2 cols) */
__device__ __align__(16) u32   g_vw[8*NB*PW];     /* wo·(v/D) fp16 B-frags  */
__device__ __align__(16) float g_v [8*48*NN];     /* fp32 v (rows 0..35)    */

/* ---------------- helpers ------------------------------------------------ */
__device__ __forceinline__ void mma_h(float* d, uint4 a, uint2 b){
    asm("mma.sync.aligned.m16n8k16.row.col.f32.f16.f16.f32 "
        "{%0,%1,%2,%3},{%4,%5,%6,%7},{%8,%9},{%0,%1,%2,%3};"
        : "+f"(d[0]), "+f"(d[1]), "+f"(d[2]), "+f"(d[3])
        : "r"(a.x), "r"(a.y), "r"(a.z), "r"(a.w), "r"(b.x), "r"(b.y));
}
__device__ __forceinline__ void mma_h16(u32* d, uint4 a, uint2 b){
    asm("mma.sync.aligned.m16n8k16.row.col.f16.f16.f16.f16 "
        "{%0,%1},{%2,%3,%4,%5},{%6,%7},{%0,%1};"
        : "+r"(d[0]), "+r"(d[1])
        : "r"(a.x), "r"(a.y), "r"(a.z), "r"(a.w), "r"(b.x), "r"(b.y));
}
__device__ __forceinline__ u32 pkh(float lo, float hi){
    __half2 h = __floats2half2_rn(lo, hi);
    return *(u32*)&h;
}
__device__ __forceinline__ u32 ex2h2(u32 x, u32 hmin){
    u32 r;
    asm("{\n\t.reg .b32 t;\n\tmin.f16x2 t, %1, %2;\n\tex2.approx.f16x2 %0, t;\n\t}"
        : "=r"(r) : "r"(x), "r"(hmin));
    return r;
}
__device__ __forceinline__ u32 smem_u32(const void* p){
    u32 a;
    asm("{ .reg .u64 t; cvta.to.shared.u64 t, %1; cvt.u32.u64 %0, t; }" : "=r"(a) : "l"(p));
    return a;
}
__device__ __forceinline__ void cpa16(u32 d, const void* s){
    asm volatile("cp.async.ca.shared.global [%0], [%1], 16;" :: "r"(d), "l"(s));
}
#define CP_COMMIT() asm volatile("cp.async.commit_group;")
#define CP_WAIT1()  asm volatile("cp.async.wait_group 1;")
#define CP_WAIT0()  asm volatile("cp.async.wait_group 0;")
#define HMIN_CONST 0x4BC04BC0u   /* {15.5h, 15.5h} */

/* ========== Kernel A: x~ / y~ / v panels; Gram precompute ================ */
__global__ __launch_bounds__(384)
void qkv_kernel(const float* __restrict__ x,
                const float* __restrict__ wq, const float* __restrict__ bq,
                const float* __restrict__ wk, const float* __restrict__ bk,
                const float* __restrict__ wv, const float* __restrict__ bv)
{
    __shared__ __align__(16) u32 stage[4096];    /* [xA|xB|yA|yB] x 1024 */
    __shared__ __align__(16) float w_s[3*432];
    __shared__ __align__(16) float b_s[3*36];
    __shared__ __align__(16) float Mg[144];      /* Wq^T Wk */
    __shared__ __align__(16) float qbk[12];      /* Wq^T bk */
    __shared__ __align__(16) float wkb[12];      /* Wk^T bq */
    __shared__ float ccs;

    const int t = threadIdx.x;
    const int grp = t >> 7, tl = t & 127;
    const int b = blockIdx.y, nblk = blockIdx.x;
    const int n = nblk*128 + tl;

    {
        const float* wsrc = (grp == 0) ? wq : (grp == 1) ? wk : wv;
        const float* bsrc = (grp == 0) ? bq : (grp == 1) ? bk : bv;
        for (int i = tl; i < 432; i += 128) w_s[grp*432 + i] = wsrc[i];
        if (tl < 36) b_s[grp*36 + tl] = bsrc[tl];
    }
    __syncthreads();

    /* Gram precompute: Mg[i][j] = sum_c Wq[c][i] Wk[c][j]; vectors; const */
    if (t < 144){
        const int i = t/12, j = t - 12*(t/12);
        float s = 0.f;
        #pragma unroll 4
        for (int c = 0; c < 36; ++c) s += w_s[c*12 + i]*w_s[432 + c*12 + j];
        Mg[t] = s;
    } else if (t < 156){
        const int i = t - 144;
        float s = 0.f;
        #pragma unroll 4
        for (int c = 0; c < 36; ++c) s += w_s[c*12 + i]*b_s[36 + c];
        qbk[i] = s;
    } else if (t < 168){
        const int i = t - 156;
        float s = 0.f;
        #pragma unroll 4
        for (int c = 0; c < 36; ++c) s += w_s[432 + c*12 + i]*b_s[c];
        wkb[i] = s;
    } else if (t == 168){
        float s = 0.f;
        #pragma unroll 4
        for (int c = 0; c < 36; ++c) s += b_s[c]*b_s[36 + c];
        ccs = s;
    }
    __syncthreads();

    float xv[12];
    #pragma unroll
    for (int c = 0; c < 12; ++c) xv[c] = x[(b*12 + c)*NN + n];

    if (grp == 2){
        /* v projection */
        const float* w = w_s + 864;
        const float* bb = b_s + 72;
        #pragma unroll 4
        for (int o = 0; o < 36; ++o){
            float acc = bb[o];
            #pragma unroll
            for (int c = 0; c < 12; ++c) acc += w[o*12 + c]*xv[c];
            g_v[((long)(b*48 + o))*NN + n] = acc;
        }
    } else {
        float val[16];
        #pragma unroll
        for (int i = 13; i < 16; ++i) val[i] = 0.f;
        if (grp == 0){
            #pragma unroll
            for (int c = 0; c < 12; ++c) val[c] = xv[c];
            val[12] = 1.0f;
        } else {
            #pragma unroll 2
            for (int i = 0; i < 12; ++i){
                float s = qbk[i];
                #pragma unroll
                for (int j = 0; j < 12; ++j) s += Mg[i*12 + j]*xv[j];
                val[i] = s*SCALE2;
            }
            float s = ccs;
            #pragma unroll
            for (int j = 0; j < 12; ++j) s += wkb[j]*xv[j];
            val[12] = s*SCALE2;
        }
        /* scatter into A + B fragment panels */
        u32* sA = stage + grp*2048;          /* grp0: xA, grp1: yA */
        u32* sB = sA + 1024;                 /* grp0: xB, grp1: yB */
        const int lr = tl & 15, rt = tl >> 4;
        const int ct = tl >> 3, gB = tl & 7;
        #pragma unroll
        for (int p = 0; p < 8; ++p){
            const int c0 = 2*p;
            const u32 fp = pkh(val[c0], val[c0 + 1]);
            const int regA  = ((p >> 2) << 1) | (lr >> 3);
            const int laneA = ((lr & 7) << 2) | (p & 3);
            sA[rt*128 + laneA*4 + regA] = fp;
            const int regB  = p >> 2;
            const int laneB = (gB << 2) | (p & 3);
            sB[ct*64 + laneB*2 + regB] = fp;
        }
    }
    __syncthreads();

    /* coalesced copy: 1024 uint4 -> 4 gmem panels */
    {
        const int base4 = ((b*NB + nblk)*P16) >> 2;
        const uint4* s4 = (const uint4*)stage;
        for (int i = t; i < 1024; i += 384){
            const int seg = i >> 8, off = i & 255;
            uint4* dst = (seg == 0) ? (uint4*)g_xA : (seg == 1) ? (uint4*)g_xB
                       : (seg == 2) ? (uint4*)g_yA : (uint4*)g_yB;
            dst[base4 + off] = s4[i];
        }
    }
}

/* ====== Pass 1: S(n,m) = y~_n · x~_m -> D[n] -> vw = wo·(v/D) ============ */
/* 512 thr = 16 warps: wg = w>>2 owns n-rows wg*32..+31 (2 A-tiles);
   h = w&3 owns m-quarter. One k16 mma per 16x8 tile.                       */
__global__ __launch_bounds__(512)
void pass1_kernel(const float* __restrict__ wo)
{
    __shared__ __align__(16) char ubuf[26624];   /* qb[3][1024]u32 | vstage+vw */
    __shared__ __align__(16) float Dsh[512];
    __shared__ __align__(16) float invd[128];
    __shared__ __align__(16) float wo_s[432];

    u32* qb = (u32*)ubuf;

    const int t = threadIdx.x, w = t >> 5, lane = t & 31;
    const int wg = w >> 2, h = w & 3;
    const int g = lane >> 2, tg = lane & 3;
    const int b = blockIdx.y, nblk = blockIdx.x;
    const u32 hmin = HMIN_CONST;

    for (int i = t; i < 432; i += 512) wo_s[i] = wo[i];

    /* y~ A-frags: 2 tiles (n-rows wg*32..+31), single k-step */
    uint4 a0f, a1f;
    {
        const u32* yA = g_yA + (b*NB + nblk)*P16;
        a0f = *(const uint4*)(yA + (wg*2 + 0)*128 + lane*4);
        a1f = *(const uint4*)(yA + (wg*2 + 1)*128 + lane*4);
    }

    const char* xsrc = (const char*)(g_xB + (long)b*NB*P16);
    {
        if (t < 256) cpa16(smem_u32(qb) + t*16, xsrc + t*16);
        CP_COMMIT();
        if (t < 256) cpa16(smem_u32(qb + P16) + t*16, xsrc + (long)P16*4 + t*16);
        CP_COMMIT();
    }

    float rs00 = 0.f, rs01 = 0.f, rs10 = 0.f, rs11 = 0.f;
    int buf = 0;

    for (int mc = 0; mc < NB; ++mc){
        CP_WAIT1();
        __syncthreads();
        if (mc + 2 < NB){
            const int nb2 = (buf + 2 >= 3) ? buf - 1 : buf + 2;
            if (t < 256) cpa16(smem_u32(qb + nb2*P16) + t*16,
                               xsrc + (long)(mc + 2)*P16*4 + t*16);
        }
        CP_COMMIT();

        const u32* cur = qb + buf*P16;
        #pragma unroll
        for (int cl = 0; cl < 4; ++cl){
            const int ctb = h*4 + cl;
            const uint2 xb = *(const uint2*)(cur + ctb*64 + lane*2);
            {
                u32 s[2] = {0u, 0u};
                mma_h16(s, a0f, xb);
                const u32 ea = ex2h2(s[0], hmin);
                const u32 eb = ex2h2(s[1], hmin);
                const float2 fa = __half22float2(*(const __half2*)&ea);
                const float2 fb = __half22float2(*(const __half2*)&eb);
                rs00 += fa.x + fa.y;
                rs01 += fb.x + fb.y;
            }
            {
                u32 s[2] = {0u, 0u};
                mma_h16(s, a1f, xb);
                const u32 ea = ex2h2(s[0], hmin);
                const u32 eb = ex2h2(s[1], hmin);
                const float2 fa = __half22float2(*(const __half2*)&ea);
                const float2 fb = __half22float2(*(const __half2*)&eb);
                rs10 += fa.x + fa.y;
                rs11 += fb.x + fb.y;
            }
        }
        buf = (buf + 1 >= 3) ? 0 : buf + 1;
    }

    rs00 += __shfl_xor_sync(0xFFFFFFFFu, rs00, 1);
    rs00 += __shfl_xor_sync(0xFFFFFFFFu, rs00, 2);
    rs01 += __shfl_xor_sync(0xFFFFFFFFu, rs01, 1);
    rs01 += __shfl_xor_sync(0xFFFFFFFFu, rs01, 2);
    rs10 += __shfl_xor_sync(0xFFFFFFFFu, rs10, 1);
    rs10 += __shfl_xor_sync(0xFFFFFFFFu, rs10, 2);
    rs11 += __shfl_xor_sync(0xFFFFFFFFu, rs11, 1);
    rs11 += __shfl_xor_sync(0xFFFFFFFFu, rs11, 2);
    if (tg == 0){
        Dsh[h*128 + wg*32 + g]      = rs00;
        Dsh[h*128 + wg*32 + 8 + g]  = rs01;
        Dsh[h*128 + wg*32 + 16 + g] = rs10;
        Dsh[h*128 + wg*32 + 24 + g] = rs11;
    }
    __syncthreads();
    if (t < 128) invd[t] = 1.0f / (Dsh[t] + Dsh[128 + t] + Dsh[256 + t] + Dsh[384 + t]);
    CP_WAIT0();
    __syncthreads();

    /* ---- vw = wo·(v/D): stage v, compute, write B-frag panel ---- */
    float* vstage = (float*)ubuf;            /* 36*128 floats */
    float* vw_s   = vstage + 36*128;         /* 16*128 floats */
    {
        const float* vb = g_v + (long)b*48*NN + nblk*128;
        for (int idx = t; idx < 36*128; idx += 512){
            const int c = idx >> 7, nn = idx & 127;
            vstage[idx] = vb[(long)c*NN + nn];
        }
    }
    __syncthreads();
    for (int idx = t; idx < 2048; idx += 512){
        const int o = idx >> 7, nn = idx & 127;
        float s = 0.f;
        if (o < 12){
            const float* wrow = wo_s + o*36;
            #pragma unroll 4
            for (int c = 0; c < 36; ++c) s += wrow[c]*vstage[c*128 + nn];
            s *= invd[nn];
        }
        vw_s[idx] = s;
    }
    __syncthreads();
    {
        u32* vdst = g_vw + (b*NB + nblk)*PW;
        for (int j = t; j < PW; j += 512){
            const int reg = j & 1, l5 = (j >> 1) & 31, tile = j >> 6;
            const int kk = tile >> 1, ct = tile & 1;
            const int o = ct*8 + (l5 >> 2);
            const int nn = kk*16 + (l5 & 3)*2 + reg*8;
            vdst[j] = pkh(vw_s[o*128 + nn], vw_s[o*128 + nn + 1]);
        }
    }
}

/* ====== Pass 2: S(m,n) = x~_m · y~_n -> P -> P·vw^T = out ================ */
/* 512 thr = 16 warps: wg = w>>2 owns m-rows wg*32..+31 (2 A-tiles);
   h = w&3 owns n-quarter (k16 groups h*2, h*2+1).                          */
__global__ __launch_bounds__(512)
void pass2_kernel(const float* __restrict__ bo, float* __restrict__ out)
{
    extern __shared__ __align__(16) char smraw[];
    u32* sY  = (u32*)smraw;                 /* [3][1024] u32 */
    u32* sW  = sY + 3*P16;                  /* [3][1024] u32 */
    float* bo_s = (float*)(sW + 3*PW);      /* 16 floats */
    float* outb = (float*)smraw;            /* 16*132 floats, reuse after loop */

    const int t = threadIdx.x, w = t >> 5, lane = t & 31;
    const int wg = w >> 2, h = w & 3;
    const int g = lane >> 2, tg = lane & 3;
    const int b = blockIdx.y, mt = blockIdx.x;
    const u32 hmin = HMIN_CONST;

    if (t < 12) bo_s[t] = bo[t];

    /* x~ A-frags: 2 tiles (m-rows wg*32..+31), single k-step */
    uint4 aq0, aq1;
    {
        const u32* xA = g_xA + (b*NB + mt)*P16;
        aq0 = *(const uint4*)(xA + (wg*2 + 0)*128 + lane*4);
        aq1 = *(const uint4*)(xA + (wg*2 + 1)*128 + lane*4);
    }

    const char* ysrc = (const char*)(g_yB + (long)b*NB*P16);
    const char* wsrc = (const char*)(g_vw + (long)b*NB*PW);
    {
        if (t < 256){
            cpa16(smem_u32(sY) + t*16, ysrc + t*16);
        } else {
            const int i = t - 256;
            cpa16(smem_u32(sW) + i*16, wsrc + i*16);
        }
        CP_COMMIT();
        if (t < 256){
            cpa16(smem_u32(sY + P16) + t*16, ysrc + (long)P16*4 + t*16);
        } else {
            const int i = t - 256;
            cpa16(smem_u32(sW + PW) + i*16, wsrc + (long)PW*4 + i*16);
        }
        CP_COMMIT();
    }

    float accA[2][4], accB[2][4];
    #pragma unroll
    for (int ct = 0; ct < 2; ++ct)
        #pragma unroll
        for (int i = 0; i < 4; ++i){ accA[ct][i] = 0.f; accB[ct][i] = 0.f; }

    int buf = 0;

    for (int nc = 0; nc < NB; ++nc){
        CP_WAIT1();
        __syncthreads();
        if (nc + 2 < NB){
            const int nb2 = (buf + 2 >= 3) ? buf - 1 : buf + 2;
            if (t < 256){
                cpa16(smem_u32(sY + nb2*P16) + t*16, ysrc + (long)(nc + 2)*P16*4 + t*16);
            } else {
                const int i = t - 256;
                cpa16(smem_u32(sW + nb2*PW) + i*16, wsrc + (long)(nc + 2)*PW*4 + i*16);
            }
        }
        CP_COMMIT();

        const u32* curY = sY + buf*P16;
        const u32* curW = sW + buf*PW;

        #pragma unroll
        for (int jj = 0; jj < 2; ++jj){
            const int kk = h*2 + jj;
            const uint2 yb0 = *(const uint2*)(curY + (2*kk    )*64 + lane*2);
            const uint2 yb1 = *(const uint2*)(curY + (2*kk + 1)*64 + lane*2);
            const uint2 bw0 = *(const uint2*)(curW + (kk*2 + 0)*64 + lane*2);
            const uint2 bw1 = *(const uint2*)(curW + (kk*2 + 1)*64 + lane*2);

            {   /* A-tile 0 */
                u32 s0[2] = {0u, 0u}, s1[2] = {0u, 0u};
                mma_h16(s0, aq0, yb0);
                mma_h16(s1, aq0, yb1);
                uint4 pf;
                pf.x = ex2h2(s0[0], hmin);
                pf.y = ex2h2(s0[1], hmin);
                pf.z = ex2h2(s1[0], hmin);
                pf.w = ex2h2(s1[1], hmin);
                mma_h(accA[0], pf, bw0);
                mma_h(accA[1], pf, bw1);
            }
            {   /* A-tile 1 */
                u32 s0[2] = {0u, 0u}, s1[2] = {0u, 0u};
                mma_h16(s0, aq1, yb0);
                mma_h16(s1, aq1, yb1);
                uint4 pf;
                pf.x = ex2h2(s0[0], hmin);
                pf.y = ex2h2(s0[1], hmin);
                pf.z = ex2h2(s1[0], hmin);
                pf.w = ex2h2(s1[1], hmin);
                mma_h(accB[0], pf, bw0);
                mma_h(accB[1], pf, bw1);
            }
        }
        buf = (buf + 1 >= 3) ? 0 : buf + 1;
    }

    CP_WAIT0();
    __syncthreads();
    #pragma unroll
    for (int ph = 0; ph < 4; ++ph){
        if (h == ph){
            #pragma unroll
            for (int ct = 0; ct < 2; ++ct){
                const int mA = wg*32 + g, mB = mA + 16, cb = ct*8 + 2*tg;
                if (ph == 0){
                    outb[cb*132 + mA]           = accA[ct][0];
                    outb[(cb + 1)*132 + mA]     = accA[ct][1];
                    outb[cb*132 + mA + 8]       = accA[ct][2];
                    outb[(cb + 1)*132 + mA + 8] = accA[ct][3];
                    outb[cb*132 + mB]           = accB[ct][0];
                    outb[(cb + 1)*132 + mB]     = accB[ct][1];
                    outb[cb*132 + mB + 8]       = accB[ct][2];
                    outb[(cb + 1)*132 + mB + 8] = accB[ct][3];
                } else {
                    outb[cb*132 + mA]           += accA[ct][0];
                    outb[(cb + 1)*132 + mA]     += accA[ct][1];
                    outb[cb*132 + mA + 8]       += accA[ct][2];
                    outb[(cb + 1)*132 + mA + 8] += accA[ct][3];
                    outb[cb*132 + mB]           += accB[ct][0];
                    outb[(cb + 1)*132 + mB]     += accB[ct][1];
                    outb[cb*132 + mB + 8]       += accB[ct][2];
                    outb[(cb + 1)*132 + mB + 8] += accB[ct][3];
                }
            }
        }
        __syncthreads();
    }

    {
        const int og = t >> 7, m = t & 127;
        #pragma unroll
        for (int oo = 0; oo < 3; ++oo){
            const int o = og*3 + oo;
            out[((long)(b*12 + o))*NN + mt*128 + m] = outb[o*132 + m] + bo_s[o];
        }
    }
}

/* ============================== launch =================================== */
extern "C" void kernel_launch(void* const* d_in, const int* in_sizes, int n_in,
                              void* d_out, int out_size)
{
    const float* x  = (const float*)d_in[0];
    const float* wq = (const float*)d_in[1];
    const float* bq = (const float*)d_in[2];
    const float* wk = (const float*)d_in[3];
    const float* bk = (const float*)d_in[4];
    const float* wv = (const float*)d_in[5];
    const float* bv = (const float*)d_in[6];
    const float* wo = (const float*)d_in[7];
    const float* bo = (const float*)d_in[8];
    float* out = (float*)d_out;

    /* pass2 dyn smem: 3*P16*4 + 3*PW*4 + 64 = 24640 */
    cudaFuncSetAttribute(pass2_kernel,
                         cudaFuncAttributeMaxDynamicSharedMemorySize, 24640);

    qkv_kernel  <<<dim3(NB, 8), 384>>>(x, wq, bq, wk, bk, wv, bv);
    pass1_kernel<<<dim3(NB, 8), 512>>>(wo);
    pass2_kernel<<<dim3(NB, 8), 512, 24640>>>(bo, out);
}

// round 17
// speedup vs baseline: 3.0643x; 1.0979x over previous
#include <cuda_runtime.h>
#include <cuda_fp16.h>
#include <cstdint>

#define NN 4096
#define NB 32
#define P16 1024     /* u32 per 16-k fragment panel (128 rows/cols) */
#define PW 1024      /* u32 per vw B-frag panel */
#define SCALE2 (0.28867513459481287f * 1.4426950408889634f)  /* (1/sqrt12)*log2e */

typedef unsigned int u32;

/* ---------------- global scratch ----------------------------------------- */
__device__ __align__(16) u32   g_xA[8*NB*P16];    /* x~ A-frags (pass2 rows) */
__device__ __align__(16) u32   g_xB[8*NB*P16];    /* x~ B-frags (pass1 cols) */
__device__ __align__(16) u32   g_yA[8*NB*P16];    /* y~ A-frags (pass1 rows) */
__device__ __align__(16) u32   g_yB[8*NB*P16];    /* y~ B-frags (pass2 cols) */
__device__ __align__(16) u32   g_vw[8*NB*PW];     /* wo·(v/D) fp16 B-frags  */
__device__ __align__(16) float g_v [8*48*NN];     /* fp32 v (rows 0..35)    */

/* ---------------- helpers ------------------------------------------------ */
__device__ __forceinline__ void mma_h(float* d, uint4 a, uint2 b){
    asm("mma.sync.aligned.m16n8k16.row.col.f32.f16.f16.f32 "
        "{%0,%1,%2,%3},{%4,%5,%6,%7},{%8,%9},{%0,%1,%2,%3};"
        : "+f"(d[0]), "+f"(d[1]), "+f"(d[2]), "+f"(d[3])
        : "r"(a.x), "r"(a.y), "r"(a.z), "r"(a.w), "r"(b.x), "r"(b.y));
}
__device__ __forceinline__ void mma_h16(u32* d, uint4 a, uint2 b){
    asm("mma.sync.aligned.m16n8k16.row.col.f16.f16.f16.f16 "
        "{%0,%1},{%2,%3,%4,%5},{%6,%7},{%0,%1};"
        : "+r"(d[0]), "+r"(d[1])
        : "r"(a.x), "r"(a.y), "r"(a.z), "r"(a.w), "r"(b.x), "r"(b.y));
}
__device__ __forceinline__ u32 pkh(float lo, float hi){
    __half2 h = __floats2half2_rn(lo, hi);
    return *(u32*)&h;
}
__device__ __forceinline__ u32 ex2h2(u32 x, u32 hmin){
    u32 r;
    asm("{\n\t.reg .b32 t;\n\tmin.f16x2 t, %1, %2;\n\tex2.approx.f16x2 %0, t;\n\t}"
        : "=r"(r) : "r"(x), "r"(hmin));
    return r;
}
__device__ __forceinline__ u32 smem_u32(const void* p){
    u32 a;
    asm("{ .reg .u64 t; cvta.to.shared.u64 t, %1; cvt.u32.u64 %0, t; }" : "=r"(a) : "l"(p));
    return a;
}
__device__ __forceinline__ void cpa16(u32 d, const void* s){
    asm volatile("cp.async.ca.shared.global [%0], [%1], 16;" :: "r"(d), "l"(s));
}
#define CP_COMMIT() asm volatile("cp.async.commit_group;")
#define CP_WAIT1()  asm volatile("cp.async.wait_group 1;")
#define CP_WAIT0()  asm volatile("cp.async.wait_group 0;")
#define HMIN_CONST 0x4BC04BC0u   /* {15.5h, 15.5h} */
#define ONES_H2    0x3C003C00u   /* {1.0h, 1.0h} */

/* ========== Kernel A: x~ / y~ / v panels; Gram precompute ================ */
__global__ __launch_bounds__(384)
void qkv_kernel(const float* __restrict__ x,
                const float* __restrict__ wq, const float* __restrict__ bq,
                const float* __restrict__ wk, const float* __restrict__ bk,
                const float* __restrict__ wv, const float* __restrict__ bv)
{
    __shared__ __align__(16) u32 stage[4096];    /* [xA|xB|yA|yB] x 1024 */
    __shared__ __align__(16) float w_s[3*432];
    __shared__ __align__(16) float b_s[3*36];
    __shared__ __align__(16) float Mg[144];      /* Wq^T Wk */
    __shared__ __align__(16) float qbk[12];      /* Wq^T bk */
    __shared__ __align__(16) float wkb[12];      /* Wk^T bq */
    __shared__ float ccs;

    const int t = threadIdx.x;
    const int grp = t >> 7, tl = t & 127;
    const int b = blockIdx.y, nblk = blockIdx.x;
    const int n = nblk*128 + tl;

    {
        const float* wsrc = (grp == 0) ? wq : (grp == 1) ? wk : wv;
        const float* bsrc = (grp == 0) ? bq : (grp == 1) ? bk : bv;
        for (int i = tl; i < 432; i += 128) w_s[grp*432 + i] = wsrc[i];
        if (tl < 36) b_s[grp*36 + tl] = bsrc[tl];
    }
    __syncthreads();

    if (t < 144){
        const int i = t/12, j = t - 12*(t/12);
        float s = 0.f;
        #pragma unroll 4
        for (int c = 0; c < 36; ++c) s += w_s[c*12 + i]*w_s[432 + c*12 + j];
        Mg[t] = s;
    } else if (t < 156){
        const int i = t - 144;
        float s = 0.f;
        #pragma unroll 4
        for (int c = 0; c < 36; ++c) s += w_s[c*12 + i]*b_s[36 + c];
        qbk[i] = s;
    } else if (t < 168){
        const int i = t - 156;
        float s = 0.f;
        #pragma unroll 4
        for (int c = 0; c < 36; ++c) s += w_s[432 + c*12 + i]*b_s[c];
        wkb[i] = s;
    } else if (t == 168){
        float s = 0.f;
        #pragma unroll 4
        for (int c = 0; c < 36; ++c) s += b_s[c]*b_s[36 + c];
        ccs = s;
    }
    __syncthreads();

    float xv[12];
    #pragma unroll
    for (int c = 0; c < 12; ++c) xv[c] = x[(b*12 + c)*NN + n];

    if (grp == 2){
        const float* w = w_s + 864;
        const float* bb = b_s + 72;
        #pragma unroll 4
        for (int o = 0; o < 36; ++o){
            float acc = bb[o];
            #pragma unroll
            for (int c = 0; c < 12; ++c) acc += w[o*12 + c]*xv[c];
            g_v[((long)(b*48 + o))*NN + n] = acc;
        }
    } else {
        float val[16];
        #pragma unroll
        for (int i = 13; i < 16; ++i) val[i] = 0.f;
        if (grp == 0){
            #pragma unroll
            for (int c = 0; c < 12; ++c) val[c] = xv[c];
            val[12] = 1.0f;
        } else {
            #pragma unroll 2
            for (int i = 0; i < 12; ++i){
                float s = qbk[i];
                #pragma unroll
                for (int j = 0; j < 12; ++j) s += Mg[i*12 + j]*xv[j];
                val[i] = s*SCALE2;
            }
            float s = ccs;
            #pragma unroll
            for (int j = 0; j < 12; ++j) s += wkb[j]*xv[j];
            val[12] = s*SCALE2;
        }
        u32* sA = stage + grp*2048;
        u32* sB = sA + 1024;
        const int lr = tl & 15, rt = tl >> 4;
        const int ct = tl >> 3, gB = tl & 7;
        #pragma unroll
        for (int p = 0; p < 8; ++p){
            const int c0 = 2*p;
            const u32 fp = pkh(val[c0], val[c0 + 1]);
            const int regA  = ((p >> 2) << 1) | (lr >> 3);
            const int laneA = ((lr & 7) << 2) | (p & 3);
            sA[rt*128 + laneA*4 + regA] = fp;
            const int regB  = p >> 2;
            const int laneB = (gB << 2) | (p & 3);
            sB[ct*64 + laneB*2 + regB] = fp;
        }
    }
    __syncthreads();

    {
        const int base4 = ((b*NB + nblk)*P16) >> 2;
        const uint4* s4 = (const uint4*)stage;
        for (int i = t; i < 1024; i += 384){
            const int seg = i >> 8, off = i & 255;
            uint4* dst = (seg == 0) ? (uint4*)g_xA : (seg == 1) ? (uint4*)g_xB
                       : (seg == 2) ? (uint4*)g_yA : (uint4*)g_yB;
            dst[base4 + off] = s4[i];
        }
    }
}

/* ====== Pass 1: S(n,m) = y~_n·x~_m -> D via ones-mma -> vw panel ========= */
/* 512 thr = 16 warps: wg = w>>2 owns n-rows wg*32..+31 (2 A-tiles);
   h = w&3 owns m-quarter. Row sums via P x ones HMMA (f32 accum).          */
__global__ __launch_bounds__(512, 2)
void pass1_kernel(const float* __restrict__ wo)
{
    __shared__ __align__(16) char ubuf[26624];   /* qb[3][1024]u32 | vstage+vw */
    __shared__ __align__(16) float Dsh[512];
    __shared__ __align__(16) float invd[128];
    __shared__ __align__(16) float wo_s[432];

    u32* qb = (u32*)ubuf;

    const int t = threadIdx.x, w = t >> 5, lane = t & 31;
    const int wg = w >> 2, h = w & 3;
    const int g = lane >> 2, tg = lane & 3;
    const int b = blockIdx.y, nblk = blockIdx.x;
    const u32 hmin = HMIN_CONST;
    const uint2 ones = make_uint2(ONES_H2, ONES_H2);

    for (int i = t; i < 432; i += 512) wo_s[i] = wo[i];

    uint4 a0f, a1f;
    {
        const u32* yA = g_yA + (b*NB + nblk)*P16;
        a0f = *(const uint4*)(yA + (wg*2 + 0)*128 + lane*4);
        a1f = *(const uint4*)(yA + (wg*2 + 1)*128 + lane*4);
    }

    const char* xsrc = (const char*)(g_xB + (long)b*NB*P16);
    {
        if (t < 256) cpa16(smem_u32(qb) + t*16, xsrc + t*16);
        CP_COMMIT();
        if (t < 256) cpa16(smem_u32(qb + P16) + t*16, xsrc + (long)P16*4 + t*16);
        CP_COMMIT();
    }

    float acc0[4] = {0.f, 0.f, 0.f, 0.f};   /* D partials, A-tile 0 */
    float acc1[4] = {0.f, 0.f, 0.f, 0.f};   /* D partials, A-tile 1 */
    int buf = 0;

    for (int mc = 0; mc < NB; ++mc){
        CP_WAIT1();
        __syncthreads();
        if (mc + 2 < NB){
            const int nb2 = (buf + 2 >= 3) ? buf - 1 : buf + 2;
            if (t < 256) cpa16(smem_u32(qb + nb2*P16) + t*16,
                               xsrc + (long)(mc + 2)*P16*4 + t*16);
        }
        CP_COMMIT();

        const u32* cur = qb + buf*P16;
        #pragma unroll
        for (int jj = 0; jj < 2; ++jj){
            const int ctb0 = h*4 + 2*jj, ctb1 = ctb0 + 1;
            const uint2 xb0 = *(const uint2*)(cur + ctb0*64 + lane*2);
            const uint2 xb1 = *(const uint2*)(cur + ctb1*64 + lane*2);
            {   /* A-tile 0: S -> exp -> P x ones accumulates row sums */
                u32 s0[2] = {0u, 0u}, s1[2] = {0u, 0u};
                mma_h16(s0, a0f, xb0);
                mma_h16(s1, a0f, xb1);
                uint4 pf;
                pf.x = ex2h2(s0[0], hmin);
                pf.y = ex2h2(s0[1], hmin);
                pf.z = ex2h2(s1[0], hmin);
                pf.w = ex2h2(s1[1], hmin);
                mma_h(acc0, pf, ones);
            }
            {   /* A-tile 1 */
                u32 s0[2] = {0u, 0u}, s1[2] = {0u, 0u};
                mma_h16(s0, a1f, xb0);
                mma_h16(s1, a1f, xb1);
                uint4 pf;
                pf.x = ex2h2(s0[0], hmin);
                pf.y = ex2h2(s0[1], hmin);
                pf.z = ex2h2(s1[0], hmin);
                pf.w = ex2h2(s1[1], hmin);
                mma_h(acc1, pf, ones);
            }
        }
        buf = (buf + 1 >= 3) ? 0 : buf + 1;
    }

    /* all output cols identical -> no shuffle; tg==0 lanes publish */
    if (tg == 0){
        Dsh[h*128 + wg*32 + g]      = acc0[0];
        Dsh[h*128 + wg*32 + 8 + g]  = acc0[2];
        Dsh[h*128 + wg*32 + 16 + g] = acc1[0];
        Dsh[h*128 + wg*32 + 24 + g] = acc1[2];
    }
    __syncthreads();
    if (t < 128) invd[t] = 1.0f / (Dsh[t] + Dsh[128 + t] + Dsh[256 + t] + Dsh[384 + t]);
    CP_WAIT0();
    __syncthreads();

    /* ---- vw = wo·(v/D): stage v, compute, write B-frag panel ---- */
    float* vstage = (float*)ubuf;            /* 36*128 floats */
    float* vw_s   = vstage + 36*128;         /* 16*128 floats */
    {
        const float* vb = g_v + (long)b*48*NN + nblk*128;
        for (int idx = t; idx < 36*128; idx += 512){
            const int c = idx >> 7, nn = idx & 127;
            vstage[idx] = vb[(long)c*NN + nn];
        }
    }
    __syncthreads();
    for (int idx = t; idx < 2048; idx += 512){
        const int o = idx >> 7, nn = idx & 127;
        float s = 0.f;
        if (o < 12){
            const float* wrow = wo_s + o*36;
            #pragma unroll 4
            for (int c = 0; c < 36; ++c) s += wrow[c]*vstage[c*128 + nn];
            s *= invd[nn];
        }
        vw_s[idx] = s;
    }
    __syncthreads();
    {
        u32* vdst = g_vw + (b*NB + nblk)*PW;
        for (int j = t; j < PW; j += 512){
            const int reg = j & 1, l5 = (j >> 1) & 31, tile = j >> 6;
            const int kk = tile >> 1, ct = tile & 1;
            const int o = ct*8 + (l5 >> 2);
            const int nn = kk*16 + (l5 & 3)*2 + reg*8;
            vdst[j] = pkh(vw_s[o*128 + nn], vw_s[o*128 + nn + 1]);
        }
    }
}

/* ====== Pass 2: S(m,n) = x~_m·y~_n -> P -> P·vw^T = out ================== */
__global__ __launch_bounds__(512, 2)
void pass2_kernel(const float* __restrict__ bo, float* __restrict__ out)
{
    extern __shared__ __align__(16) char smraw[];
    u32* sY  = (u32*)smraw;                 /* [3][1024] u32 */
    u32* sW  = sY + 3*P16;                  /* [3][1024] u32 */
    float* bo_s = (float*)(sW + 3*PW);      /* 16 floats */
    float* outb = (float*)smraw;            /* 16*132 floats, reuse after loop */

    const int t = threadIdx.x, w = t >> 5, lane = t & 31;
    const int wg = w >> 2, h = w & 3;
    const int g = lane >> 2, tg = lane & 3;
    const int b = blockIdx.y, mt = blockIdx.x;
    const u32 hmin = HMIN_CONST;

    if (t < 12) bo_s[t] = bo[t];

    uint4 aq0, aq1;
    {
        const u32* xA = g_xA + (b*NB + mt)*P16;
        aq0 = *(const uint4*)(xA + (wg*2 + 0)*128 + lane*4);
        aq1 = *(const uint4*)(xA + (wg*2 + 1)*128 + lane*4);
    }

    const char* ysrc = (const char*)(g_yB + (long)b*NB*P16);
    const char* wsrc = (const char*)(g_vw + (long)b*NB*PW);
    {
        if (t < 256){
            cpa16(smem_u32(sY) + t*16, ysrc + t*16);
        } else {
            const int i = t - 256;
            cpa16(smem_u32(sW) + i*16, wsrc + i*16);
        }
        CP_COMMIT();
        if (t < 256){
            cpa16(smem_u32(sY + P16) + t*16, ysrc + (long)P16*4 + t*16);
        } else {
            const int i = t - 256;
            cpa16(smem_u32(sW + PW) + i*16, wsrc + (long)PW*4 + i*16);
        }
        CP_COMMIT();
    }

    float accA[2][4], accB[2][4];
    #pragma unroll
    for (int ct = 0; ct < 2; ++ct)
        #pragma unroll
        for (int i = 0; i < 4; ++i){ accA[ct][i] = 0.f; accB[ct][i] = 0.f; }

    int buf = 0;

    for (int nc = 0; nc < NB; ++nc){
        CP_WAIT1();
        __syncthreads();
        if (nc + 2 < NB){
            const int nb2 = (buf + 2 >= 3) ? buf - 1 : buf + 2;
            if (t < 256){
                cpa16(smem_u32(sY + nb2*P16) + t*16, ysrc + (long)(nc + 2)*P16*4 + t*16);
            } else {
                const int i = t - 256;
                cpa16(smem_u32(sW + nb2*PW) + i*16, wsrc + (long)(nc + 2)*PW*4 + i*16);
            }
        }
        CP_COMMIT();

        const u32* curY = sY + buf*P16;
        const u32* curW = sW + buf*PW;

        #pragma unroll
        for (int jj = 0; jj < 2; ++jj){
            const int kk = h*2 + jj;
            const uint2 yb0 = *(const uint2*)(curY + (2*kk    )*64 + lane*2);
            const uint2 yb1 = *(const uint2*)(curY + (2*kk + 1)*64 + lane*2);
            const uint2 bw0 = *(const uint2*)(curW + (kk*2 + 0)*64 + lane*2);
            const uint2 bw1 = *(const uint2*)(curW + (kk*2 + 1)*64 + lane*2);

            {   /* A-tile 0 */
                u32 s0[2] = {0u, 0u}, s1[2] = {0u, 0u};
                mma_h16(s0, aq0, yb0);
                mma_h16(s1, aq0, yb1);
                uint4 pf;
                pf.x = ex2h2(s0[0], hmin);
                pf.y = ex2h2(s0[1], hmin);
                pf.z = ex2h2(s1[0], hmin);
                pf.w = ex2h2(s1[1], hmin);
                mma_h(accA[0], pf, bw0);
                mma_h(accA[1], pf, bw1);
            }
            {   /* A-tile 1 */
                u32 s0[2] = {0u, 0u}, s1[2] = {0u, 0u};
                mma_h16(s0, aq1, yb0);
                mma_h16(s1, aq1, yb1);
                uint4 pf;
                pf.x = ex2h2(s0[0], hmin);
                pf.y = ex2h2(s0[1], hmin);
                pf.z = ex2h2(s1[0], hmin);
                pf.w = ex2h2(s1[1], hmin);
                mma_h(accB[0], pf, bw0);
                mma_h(accB[1], pf, bw1);
            }
        }
        buf = (buf + 1 >= 3) ? 0 : buf + 1;
    }

    CP_WAIT0();
    __syncthreads();
    #pragma unroll
    for (int ph = 0; ph < 4; ++ph){
        if (h == ph){
            #pragma unroll
            for (int ct = 0; ct < 2; ++ct){
                const int mA = wg*32 + g, mB = mA + 16, cb = ct*8 + 2*tg;
                if (ph == 0){
                    outb[cb*132 + mA]           = accA[ct][0];
                    outb[(cb + 1)*132 + mA]     = accA[ct][1];
                    outb[cb*132 + mA + 8]       = accA[ct][2];
                    outb[(cb + 1)*132 + mA + 8] = accA[ct][3];
                    outb[cb*132 + mB]           = accB[ct][0];
                    outb[(cb + 1)*132 + mB]     = accB[ct][1];
                    outb[cb*132 + mB + 8]       = accB[ct][2];
                    outb[(cb + 1)*132 + mB + 8] = accB[ct][3];
                } else {
                    outb[cb*132 + mA]           += accA[ct][0];
                    outb[(cb + 1)*132 + mA]     += accA[ct][1];
                    outb[cb*132 + mA + 8]       += accA[ct][2];
                    outb[(cb + 1)*132 + mA + 8] += accA[ct][3];
                    outb[cb*132 + mB]           += accB[ct][0];
                    outb[(cb + 1)*132 + mB]     += accB[ct][1];
                    outb[cb*132 + mB + 8]       += accB[ct][2];
                    outb[(cb + 1)*132 + mB + 8] += accB[ct][3];
                }
            }
        }
        __syncthreads();
    }

    {
        const int og = t >> 7, m = t & 127;
        #pragma unroll
        for (int oo = 0; oo < 3; ++oo){
            const int o = og*3 + oo;
            out[((long)(b*12 + o))*NN + mt*128 + m] = outb[o*132 + m] + bo_s[o];
        }
    }
}

/* ============================== launch =================================== */
extern "C" void kernel_launch(void* const* d_in, const int* in_sizes, int n_in,
                              void* d_out, int out_size)
{
    const float* x  = (const float*)d_in[0];
    const float* wq = (const float*)d_in[1];
    const float* bq = (const float*)d_in[2];
    const float* wk = (const float*)d_in[3];
    const float* bk = (const float*)d_in[4];
    const float* wv = (const float*)d_in[5];
    const float* bv = (const float*)d_in[6];
    const float* wo = (const float*)d_in[7];
    const float* bo = (const float*)d_in[8];
    float* out = (float*)d_out;

    /* pass2 dyn smem: 3*P16*4 + 3*PW*4 + 64 = 24640 */
    cudaFuncSetAttribute(pass2_kernel,
                         cudaFuncAttributeMaxDynamicSharedMemorySize, 24640);

    qkv_kernel  <<<dim3(NB, 8), 384>>>(x, wq, bq, wk, bk, wv, bv);
    pass1_kernel<<<dim3(NB, 8), 512>>>(wo);
    pass2_kernel<<<dim3(NB, 8), 512, 24640>>>(bo, out);
}